// round 1
// baseline (speedup 1.0000x reference)
#include <cuda_runtime.h>

// KLLoss: out = mean over rows of -sum_y target[r,y] * log_softmax(pred[r])[y]
// N = 4194304 rows, C = 10. Pure HBM-bound: 335.5 MB read -> ~42us floor on GB300.
//
// Layout trick: one row = 40B (not 16B aligned), but 2 rows = 80B = 5 aligned
// float4s. Each thread handles 2 rows with 5+5 LDG.128 (160B), fully coalesced.

#define C 10

__global__ void kl_zero_kernel(float* out) {
    if (threadIdx.x == 0) out[0] = 0.0f;
}

__global__ __launch_bounds__(256) void kl_loss_kernel(
    const float4* __restrict__ pred4,
    const float4* __restrict__ tgt4,
    float* __restrict__ out,
    int n_pairs,        // N/2
    float inv_n)        // 1/N
{
    int i = blockIdx.x * blockDim.x + threadIdx.x;
    float acc = 0.0f;

    if (i < n_pairs) {
        // Load 2 rows = 20 floats = 5 float4s, for pred and target.
        float p[20], t[20];
        long base = (long)i * 5;
        #pragma unroll
        for (int j = 0; j < 5; j++) {
            float4 v = pred4[base + j];
            p[4*j+0] = v.x; p[4*j+1] = v.y; p[4*j+2] = v.z; p[4*j+3] = v.w;
        }
        #pragma unroll
        for (int j = 0; j < 5; j++) {
            float4 v = tgt4[base + j];
            t[4*j+0] = v.x; t[4*j+1] = v.y; t[4*j+2] = v.z; t[4*j+3] = v.w;
        }

        #pragma unroll
        for (int r = 0; r < 2; r++) {
            const float* pr = p + r * C;
            const float* tr = t + r * C;
            // max
            float m = pr[0];
            #pragma unroll
            for (int y = 1; y < C; y++) m = fmaxf(m, pr[y]);
            // sum exp, sum target, dot(target, pred)
            float s = 0.0f, st = 0.0f, dp = 0.0f;
            #pragma unroll
            for (int y = 0; y < C; y++) {
                s  += __expf(pr[y] - m);
                st += tr[y];
                dp  = fmaf(tr[y], pr[y], dp);
            }
            float lse = m + __logf(s);
            // -sum_y t*(p - lse) = lse*sum_t - dot(t,p)
            acc += lse * st - dp;
        }
    }

    // Warp reduce
    #pragma unroll
    for (int off = 16; off > 0; off >>= 1)
        acc += __shfl_xor_sync(0xFFFFFFFFu, acc, off);

    __shared__ float ws[8];
    int lane = threadIdx.x & 31;
    int wid  = threadIdx.x >> 5;
    if (lane == 0) ws[wid] = acc;
    __syncthreads();

    if (wid == 0) {
        float v = (lane < 8) ? ws[lane] : 0.0f;
        #pragma unroll
        for (int off = 4; off > 0; off >>= 1)
            v += __shfl_xor_sync(0xFFFFFFFFu, v, off);
        if (lane == 0)
            atomicAdd(out, v * inv_n);   // REDG (no return): ~0.854 cyc/op serialized, negligible
    }
}

extern "C" void kernel_launch(void* const* d_in, const int* in_sizes, int n_in,
                              void* d_out, int out_size) {
    const float4* pred = (const float4*)d_in[0];
    const float4* tgt  = (const float4*)d_in[1];
    float* out = (float*)d_out;

    int n_rows  = in_sizes[0] / C;        // 4194304
    int n_pairs = n_rows / 2;             // 2097152 (N is even)
    float inv_n = 1.0f / (float)n_rows;

    kl_zero_kernel<<<1, 32>>>(out);
    int threads = 256;
    int blocks  = (n_pairs + threads - 1) / threads;   // 8192
    kl_loss_kernel<<<blocks, threads>>>(pred, tgt, out, n_pairs, inv_n);
}